// round 12
// baseline (speedup 1.0000x reference)
#include <cuda_runtime.h>
#include <math.h>

#define B 32
#define N 512
#define FIN 16
#define H 8
#define DH 8
#define DOUT 32

typedef unsigned long long ull;

// ---------------- scratch ----------------
__device__ float g_Wh[B*N*H*DH];          // [b][n][h*8+d]
__device__ float g_f1[B*N*H];             // [b][n][h]
__device__ float g_f2[B*N*H];             // [b][n][h]
__device__ float g_hcat[B*N*H*DH];        // [b][n][h*8+d]
__device__ float g_Who[B*N*DOUT];         // [b][n][d]
__device__ float g_g1[B*N];
__device__ float g_g2[B*N];
__device__ float g_outT[N*DOUT*B];        // [k][b], k = n*32+d
__device__ float g_qpart[128*B*N];        // split-K partials
__device__ int   g_cnt[B*N];
__device__ int   g_nbr[B*N*N];

// ---------------- helpers ----------------
__device__ __forceinline__ float lrelu(float x){ return x >= 0.f ? x : 0.2f * x; }
__device__ __forceinline__ float elu(float x){ return x > 0.f ? x : expm1f(x); }

__device__ __forceinline__ ull fma2(ull a, ull b, ull c){
    ull d;
    asm("fma.rn.f32x2 %0, %1, %2, %3;" : "=l"(d) : "l"(a), "l"(b), "l"(c));
    return d;
}
__device__ __forceinline__ ull pack2(float x){
    ull r;
    asm("mov.b64 %0, {%1, %1};" : "=l"(r) : "f"(x));
    return r;
}
__device__ __forceinline__ void unpack2(ull v, float& lo, float& hi){
    asm("mov.b64 {%0, %1}, %2;" : "=f"(lo), "=f"(hi) : "l"(v));
}

// ---------------- K0: compact adjacency rows into neighbor lists ----------------
__global__ void k0_compact(const float* __restrict__ adj){
    int t = threadIdx.x, w = t >> 5, lane = t & 31;
    int row = blockIdx.x * 8 + w;
    const float* arow = adj + (size_t)row * N;
    float av[16];
#pragma unroll
    for (int c = 0; c < 16; c++) av[c] = arow[c*32 + lane];
    unsigned bal[16];
#pragma unroll
    for (int c = 0; c < 16; c++) bal[c] = __ballot_sync(0xffffffffu, av[c] > 0.f);
    int* dst = g_nbr + (size_t)row * N;
    int base = 0;
    unsigned lmask = (1u << lane) - 1u;
#pragma unroll
    for (int c = 0; c < 16; c++){
        unsigned b = bal[c];
        if ((b >> lane) & 1u) dst[base + __popc(b & lmask)] = c*32 + lane;
        base += __popc(b);
    }
    if (lane == 0) g_cnt[row] = base;
}

// ---------------- K1: Wh = xv @ W_heads ; f1 ; f2 ----------------
__global__ void k1_proj(const float* __restrict__ xv,
                        const float* __restrict__ Wheads,
                        const float* __restrict__ a1,
                        const float* __restrict__ a2){
    __shared__ float Ws[H*FIN*DH];
    __shared__ float a1s[H*DH], a2s[H*DH];
    int t = threadIdx.x;
    for (int i = t; i < H*FIN*DH; i += 256) Ws[i] = Wheads[i];
    if (t < H*DH){ a1s[t] = a1[t]; a2s[t] = a2[t]; }
    __syncthreads();

    int gt = blockIdx.x * 256 + t;
    int h  = gt & 7;
    int bn = gt >> 3;
    const float* xr = xv + bn * FIN;

    float wh[DH];
#pragma unroll
    for (int d = 0; d < DH; d++) wh[d] = 0.f;
#pragma unroll
    for (int f = 0; f < FIN; f++){
        float x = xr[f];
        const float* wf = Ws + (h*FIN + f)*DH;
#pragma unroll
        for (int d = 0; d < DH; d++) wh[d] += x * wf[d];
    }
    float f1v = 0.f, f2v = 0.f;
#pragma unroll
    for (int d = 0; d < DH; d++){
        f1v += wh[d] * a1s[h*DH + d];
        f2v += wh[d] * a2s[h*DH + d];
    }
    float* dstp = g_Wh + (size_t)bn*64 + h*8;
    ((float4*)dstp)[0] = make_float4(wh[0], wh[1], wh[2], wh[3]);
    ((float4*)dstp)[1] = make_float4(wh[4], wh[5], wh[6], wh[7]);
    g_f1[bn*8 + h] = f1v;
    g_f2[bn*8 + h] = f2v;
}

// ---------------- K2: layer-1 attention, thread=(h,d), no max pass, chunk-8 ----------------
__global__ void k2_gat(){
    int t = threadIdx.x;
    int g = t >> 6, u = t & 63;
    int h = u >> 3;
    int row = blockIdx.x * 4 + g;
    int b = row >> 9;

    int cnt = g_cnt[row];
    const int* __restrict__ jl = g_nbr + (size_t)row * N;
    const float* __restrict__ f2B = g_f2 + (size_t)b * N * 8;
    const float* __restrict__ WhB = g_Wh + (size_t)b * N * 64;
    float f1i = g_f1[row*8 + h];

    float s = 0.f, acc = 0.f;
    if (cnt > 0){
        int k = 0;
        for (; k + 8 <= cnt; k += 8){
            int4 ja = *(const int4*)(jl + k);
            int4 jb = *(const int4*)(jl + k + 4);
            float e0 = f2B[ja.x*8 + h], e1 = f2B[ja.y*8 + h];
            float e2 = f2B[ja.z*8 + h], e3 = f2B[ja.w*8 + h];
            float e4 = f2B[jb.x*8 + h], e5 = f2B[jb.y*8 + h];
            float e6 = f2B[jb.z*8 + h], e7 = f2B[jb.w*8 + h];
            float w0 = WhB[(size_t)ja.x*64 + u], w1 = WhB[(size_t)ja.y*64 + u];
            float w2 = WhB[(size_t)ja.z*64 + u], w3 = WhB[(size_t)ja.w*64 + u];
            float w4 = WhB[(size_t)jb.x*64 + u], w5 = WhB[(size_t)jb.y*64 + u];
            float w6 = WhB[(size_t)jb.z*64 + u], w7 = WhB[(size_t)jb.w*64 + u];
            float p0 = expf(lrelu(f1i + e0)), p1 = expf(lrelu(f1i + e1));
            float p2 = expf(lrelu(f1i + e2)), p3 = expf(lrelu(f1i + e3));
            float p4 = expf(lrelu(f1i + e4)), p5 = expf(lrelu(f1i + e5));
            float p6 = expf(lrelu(f1i + e6)), p7 = expf(lrelu(f1i + e7));
            s += p0; s += p1; s += p2; s += p3;
            s += p4; s += p5; s += p6; s += p7;
            acc += p0*w0; acc += p1*w1; acc += p2*w2; acc += p3*w3;
            acc += p4*w4; acc += p5*w5; acc += p6*w6; acc += p7*w7;
        }
        for (; k < cnt; k++){
            int j = jl[k];
            float p = expf(lrelu(f1i + f2B[j*8 + h]));
            s += p;
            acc += p * WhB[(size_t)j*64 + u];
        }
    } else {
        s = (float)N;
        for (int j = 0; j < N; j++) acc += WhB[(size_t)j*64 + u];
    }
    g_hcat[(size_t)row*64 + u] = elu(acc / s);
}

// ---------------- K3: Who = h_cat @ W_out (32 rows/block, 4 rows/warp, LDG broadcast) ----------------
__global__ void k3_who(const float* __restrict__ Wout,
                       const float* __restrict__ a1o,
                       const float* __restrict__ a2o){
    __shared__ float Ws[64*32];     // 8 KB only
    __shared__ float a1s[32], a2s[32];
    int t = threadIdx.x;
    for (int i = t; i < 64*32; i += 256) Ws[i] = Wout[i];
    if (t < 32){ a1s[t] = a1o[t]; a2s[t] = a2o[t]; }
    __syncthreads();

    int w = t >> 5, lane = t & 31;
    int row0 = blockIdx.x*32 + w*4;
    const float4* h4 = (const float4*)(g_hcat + (size_t)row0*64);  // row r at h4 + r*16

    float who[4] = {0.f, 0.f, 0.f, 0.f};
#pragma unroll
    for (int f4 = 0; f4 < 16; f4++){
        float4 h0 = h4[f4];             // LDG.128 warp-broadcast
        float4 h1 = h4[16 + f4];
        float4 h2 = h4[32 + f4];
        float4 h3 = h4[48 + f4];
        float w0 = Ws[(4*f4+0)*32 + lane];
        float w1 = Ws[(4*f4+1)*32 + lane];
        float w2 = Ws[(4*f4+2)*32 + lane];
        float w3 = Ws[(4*f4+3)*32 + lane];
        who[0] += h0.x*w0 + h0.y*w1 + h0.z*w2 + h0.w*w3;
        who[1] += h1.x*w0 + h1.y*w1 + h1.z*w2 + h1.w*w3;
        who[2] += h2.x*w0 + h2.y*w1 + h2.z*w2 + h2.w*w3;
        who[3] += h3.x*w0 + h3.y*w1 + h3.z*w2 + h3.w*w3;
    }
    float a1v = a1s[lane], a2v = a2s[lane];
    float v1[4], v2[4];
#pragma unroll
    for (int r = 0; r < 4; r++){
        g_Who[(size_t)(row0+r)*32 + lane] = who[r];
        v1[r] = who[r]*a1v; v2[r] = who[r]*a2v;
    }
#pragma unroll
    for (int o = 16; o; o >>= 1)
#pragma unroll
        for (int r = 0; r < 4; r++){
            v1[r] += __shfl_xor_sync(0xffffffffu, v1[r], o);
            v2[r] += __shfl_xor_sync(0xffffffffu, v2[r], o);
        }
    if (lane == 0)
#pragma unroll
        for (int r = 0; r < 4; r++){ g_g1[row0+r] = v1[r]; g_g2[row0+r] = v2[r]; }
}

// ---------------- K4: layer-2 attention, lane=dim, no max pass, chunk-8, writes outT ----------------
__global__ void k4_outattn(){
    int t = threadIdx.x, w = t >> 5, lane = t & 31;
    int row = blockIdx.x * 8 + w;       // = b*512 + i
    int b = row >> 9, i = row & 511;
    int cnt = g_cnt[row];
    const int* __restrict__ jl = g_nbr + (size_t)row * N;

    float g1i = g_g1[row];
    const float* __restrict__ g2b  = g_g2 + b * N;
    const float* __restrict__ WhoB = g_Who + (size_t)b * N * DOUT;

    float s = 0.f, tot = 0.f;
    if (cnt > 0){
        int k = 0;
        for (; k + 8 <= cnt; k += 8){
            int4 ja = *(const int4*)(jl + k);
            int4 jb = *(const int4*)(jl + k + 4);
            float e0 = g2b[ja.x], e1 = g2b[ja.y], e2 = g2b[ja.z], e3 = g2b[ja.w];
            float e4 = g2b[jb.x], e5 = g2b[jb.y], e6 = g2b[jb.z], e7 = g2b[jb.w];
            float w0 = WhoB[(size_t)ja.x*DOUT + lane], w1 = WhoB[(size_t)ja.y*DOUT + lane];
            float w2 = WhoB[(size_t)ja.z*DOUT + lane], w3 = WhoB[(size_t)ja.w*DOUT + lane];
            float w4 = WhoB[(size_t)jb.x*DOUT + lane], w5 = WhoB[(size_t)jb.y*DOUT + lane];
            float w6 = WhoB[(size_t)jb.z*DOUT + lane], w7 = WhoB[(size_t)jb.w*DOUT + lane];
            float p0 = expf(lrelu(g1i + e0)), p1 = expf(lrelu(g1i + e1));
            float p2 = expf(lrelu(g1i + e2)), p3 = expf(lrelu(g1i + e3));
            float p4 = expf(lrelu(g1i + e4)), p5 = expf(lrelu(g1i + e5));
            float p6 = expf(lrelu(g1i + e6)), p7 = expf(lrelu(g1i + e7));
            s += p0; s += p1; s += p2; s += p3;
            s += p4; s += p5; s += p6; s += p7;
            tot += p0*w0; tot += p1*w1; tot += p2*w2; tot += p3*w3;
            tot += p4*w4; tot += p5*w5; tot += p6*w6; tot += p7*w7;
        }
        for (; k < cnt; k++){
            int j = jl[k];
            float p = expf(lrelu(g1i + g2b[j]));
            s += p;
            tot += p * WhoB[(size_t)j*DOUT + lane];
        }
    } else {
        s = (float)N;
        for (int j = 0; j < N; j++) tot += WhoB[(size_t)j*DOUT + lane];
    }
    g_outT[(size_t)(i*32 + lane)*B + b] = elu(tot / s);
}

// ---------------- K5: register-tiled GEMM  q = out[32,16384] @ Wq[16384,512] ----------------
__global__ void k5_qgemm(const float* __restrict__ Wq){
    __shared__ float outS[64*32];   // [k][b]  8 KB
    __shared__ float wqS[64*64];    // [k][c] 16 KB
    int t = threadIdx.x;
    int slice = t >> 6;             // 0..3
    int u = t & 63;
    int tx = u & 7;
    int ty = u >> 3;
    int b0 = ty*4, c0 = tx*8;
    int cb = blockIdx.x;
    int ky = blockIdx.y;
    int k0blk = ky * 512;

    ull acc2[16];
#pragma unroll
    for (int q = 0; q < 16; q++) acc2[q] = 0ull;

    for (int st = 0; st < 8; st++){
        int k0 = k0blk + st*64;
        __syncthreads();
        {
            const float4* src = (const float4*)(g_outT + (size_t)k0*32);
            float4* dst = (float4*)outS;
            dst[t]       = src[t];
            dst[t + 256] = src[t + 256];
        }
#pragma unroll
        for (int i = 0; i < 4; i++){
            int lin = t + i*256;
            int kk = lin >> 4;
            int cq = lin & 15;
            ((float4*)wqS)[kk*16 + cq] =
                *(const float4*)(Wq + (size_t)(k0 + kk)*512 + cb*64 + cq*4);
        }
        __syncthreads();

        const float* oS = outS + slice*16*32;
        const float* wS = wqS  + slice*16*64;
#pragma unroll
        for (int kk = 0; kk < 16; kk++){
            float4 o4 = *(const float4*)(oS + kk*32 + b0);
            ull ob0 = pack2(o4.x), ob1 = pack2(o4.y), ob2 = pack2(o4.z), ob3 = pack2(o4.w);
            const ull* w2 = (const ull*)(wS + kk*64 + c0);
#pragma unroll
            for (int cp = 0; cp < 4; cp++){
                ull wv = w2[cp];
                acc2[0*4+cp] = fma2(ob0, wv, acc2[0*4+cp]);
                acc2[1*4+cp] = fma2(ob1, wv, acc2[1*4+cp]);
                acc2[2*4+cp] = fma2(ob2, wv, acc2[2*4+cp]);
                acc2[3*4+cp] = fma2(ob3, wv, acc2[3*4+cp]);
            }
        }
    }
    float* qp = g_qpart + (size_t)(ky*4 + slice) * (B*N);
#pragma unroll
    for (int bb = 0; bb < 4; bb++)
#pragma unroll
        for (int cp = 0; cp < 4; cp++){
            float lo, hi; unpack2(acc2[bb*4+cp], lo, hi);
            int c = cb*64 + c0 + cp*2;
            qp[(b0+bb)*N + c]     = lo;
            qp[(b0+bb)*N + c + 1] = hi;
        }
}

// ---------------- K6: q = sum of 128 partials + b_q ----------------
__global__ void k6_reduce(const float* __restrict__ bq, float* __restrict__ q){
    int t = blockIdx.x * 128 + threadIdx.x;
    int c = t & 511;
    float s = bq[c];
#pragma unroll
    for (int p = 0; p < 128; p++) s += g_qpart[(size_t)p*(B*N) + t];
    q[t] = s;
}

// ---------------- launch ----------------
extern "C" void kernel_launch(void* const* d_in, const int* in_sizes, int n_in,
                              void* d_out, int out_size){
    const float* xv    = (const float*)d_in[0];
    const float* adj   = (const float*)d_in[1];
    const float* Whead = (const float*)d_in[2];
    const float* a1    = (const float*)d_in[3];
    const float* a2    = (const float*)d_in[4];
    const float* Wout  = (const float*)d_in[5];
    const float* a1o   = (const float*)d_in[6];
    const float* a2o   = (const float*)d_in[7];
    const float* Wq    = (const float*)d_in[8];
    const float* bq    = (const float*)d_in[9];
    float* q = (float*)d_out;

    k0_compact<<<B*N/8, 256>>>(adj);
    k1_proj   <<<512, 256>>>(xv, Whead, a1, a2);
    k2_gat    <<<B*N/4, 256>>>();
    k3_who    <<<B*N/32, 256>>>(Wout, a1o, a2o);
    k4_outattn<<<B*N/8, 256>>>();
    k5_qgemm  <<<dim3(8, 32), 256>>>(Wq);
    k6_reduce <<<128, 128>>>(bq, q);
}

// round 13
// speedup vs baseline: 1.0535x; 1.0535x over previous
#include <cuda_runtime.h>
#include <math.h>

#define B 32
#define N 512
#define FIN 16
#define H 8
#define DH 8
#define DOUT 32

typedef unsigned long long ull;
typedef unsigned short u16;

// ---------------- scratch ----------------
__device__ float g_Wh[B*N*H*DH];          // [b][n][h*8+d]
__device__ float g_f1[B*N*H];             // [b][n][h]
__device__ float g_f2[B*N*H];             // [b][n][h]
__device__ float g_Who[B*N*DOUT];         // [b][n][d]
__device__ float g_g1[B*N];
__device__ float g_g2[B*N];
__device__ float g_outT[N*DOUT*B];        // [k][b], k = n*32+d
__device__ float g_qpart[128*B*N];        // split-K partials
__device__ int   g_cnt[B*N];
__device__ u16   g_nbr[B*N*N];            // compacted neighbor lists (16-bit, 16.7 MB)

// ---------------- helpers ----------------
__device__ __forceinline__ float lrelu(float x){ return x >= 0.f ? x : 0.2f * x; }
__device__ __forceinline__ float elu(float x){ return x > 0.f ? x : expm1f(x); }
__device__ __forceinline__ float fexp(float x){ return __expf(x); }

__device__ __forceinline__ ull fma2(ull a, ull b, ull c){
    ull d;
    asm("fma.rn.f32x2 %0, %1, %2, %3;" : "=l"(d) : "l"(a), "l"(b), "l"(c));
    return d;
}
__device__ __forceinline__ ull pack2(float x){
    ull r;
    asm("mov.b64 %0, {%1, %1};" : "=l"(r) : "f"(x));
    return r;
}
__device__ __forceinline__ void unpack2(ull v, float& lo, float& hi){
    asm("mov.b64 {%0, %1}, %2;" : "=f"(lo), "=f"(hi) : "l"(v));
}

// ---------------- K0: compact adjacency rows into 16-bit neighbor lists ----------------
__global__ void k0_compact(const float* __restrict__ adj){
    int t = threadIdx.x, w = t >> 5, lane = t & 31;
    int row = blockIdx.x * 8 + w;
    const float* arow = adj + (size_t)row * N;
    float av[16];
#pragma unroll
    for (int c = 0; c < 16; c++) av[c] = arow[c*32 + lane];
    unsigned bal[16];
#pragma unroll
    for (int c = 0; c < 16; c++) bal[c] = __ballot_sync(0xffffffffu, av[c] > 0.f);
    u16* dst = g_nbr + (size_t)row * N;
    int base = 0;
    unsigned lmask = (1u << lane) - 1u;
#pragma unroll
    for (int c = 0; c < 16; c++){
        unsigned b = bal[c];
        if ((b >> lane) & 1u) dst[base + __popc(b & lmask)] = (u16)(c*32 + lane);
        base += __popc(b);
    }
    if (lane == 0) g_cnt[row] = base;
}

// ---------------- K1: Wh = xv @ W_heads ; f1 ; f2 ----------------
__global__ void k1_proj(const float* __restrict__ xv,
                        const float* __restrict__ Wheads,
                        const float* __restrict__ a1,
                        const float* __restrict__ a2){
    __shared__ float Ws[H*FIN*DH];
    __shared__ float a1s[H*DH], a2s[H*DH];
    int t = threadIdx.x;
    for (int i = t; i < H*FIN*DH; i += 256) Ws[i] = Wheads[i];
    if (t < H*DH){ a1s[t] = a1[t]; a2s[t] = a2[t]; }
    __syncthreads();

    int gt = blockIdx.x * 256 + t;
    int h  = gt & 7;
    int bn = gt >> 3;
    const float* xr = xv + bn * FIN;

    float wh[DH];
#pragma unroll
    for (int d = 0; d < DH; d++) wh[d] = 0.f;
#pragma unroll
    for (int f = 0; f < FIN; f++){
        float x = xr[f];
        const float* wf = Ws + (h*FIN + f)*DH;
#pragma unroll
        for (int d = 0; d < DH; d++) wh[d] += x * wf[d];
    }
    float f1v = 0.f, f2v = 0.f;
#pragma unroll
    for (int d = 0; d < DH; d++){
        f1v += wh[d] * a1s[h*DH + d];
        f2v += wh[d] * a2s[h*DH + d];
    }
    float* dstp = g_Wh + (size_t)bn*64 + h*8;
    ((float4*)dstp)[0] = make_float4(wh[0], wh[1], wh[2], wh[3]);
    ((float4*)dstp)[1] = make_float4(wh[4], wh[5], wh[6], wh[7]);
    g_f1[bn*8 + h] = f1v;
    g_f2[bn*8 + h] = f2v;
}

// ---------------- K2: fused layer-1 attention + Who GEMM + g1/g2 ----------------
// 4 rows/block x 64 threads; phase 1 = GAT gather (thread=(h,d)); phase 2 = row@Wout
__global__ void k2_fused(const float* __restrict__ Wout,
                         const float* __restrict__ a1o,
                         const float* __restrict__ a2o){
    __shared__ float Ws[64*32];     // 8 KB
    __shared__ float hs[4][64];     // per-row hcat
    __shared__ float a1s[32], a2s[32];
    int t = threadIdx.x;
    for (int i = t; i < 64*32; i += 256) Ws[i] = Wout[i];
    if (t < 32){ a1s[t] = a1o[t]; a2s[t] = a2o[t]; }

    int g = t >> 6, u = t & 63;
    int h = u >> 3;
    int row = blockIdx.x * 4 + g;
    int b = row >> 9;

    int cnt = g_cnt[row];
    const u16* __restrict__ jl = g_nbr + (size_t)row * N;
    const float* __restrict__ f2B = g_f2 + (size_t)b * N * 8;
    const float* __restrict__ WhB = g_Wh + (size_t)b * N * 64;
    float f1i = g_f1[row*8 + h];

    float s = 0.f, acc = 0.f;
    if (cnt > 0){
        int k = 0;
        for (; k + 8 <= cnt; k += 8){
            uint4 v = *(const uint4*)(jl + k);
            int j0 = v.x & 0xFFFF, j1 = v.x >> 16;
            int j2 = v.y & 0xFFFF, j3 = v.y >> 16;
            int j4 = v.z & 0xFFFF, j5 = v.z >> 16;
            int j6 = v.w & 0xFFFF, j7 = v.w >> 16;
            float e0 = f2B[j0*8 + h], e1 = f2B[j1*8 + h];
            float e2 = f2B[j2*8 + h], e3 = f2B[j3*8 + h];
            float e4 = f2B[j4*8 + h], e5 = f2B[j5*8 + h];
            float e6 = f2B[j6*8 + h], e7 = f2B[j7*8 + h];
            float w0 = WhB[(size_t)j0*64 + u], w1 = WhB[(size_t)j1*64 + u];
            float w2 = WhB[(size_t)j2*64 + u], w3 = WhB[(size_t)j3*64 + u];
            float w4 = WhB[(size_t)j4*64 + u], w5 = WhB[(size_t)j5*64 + u];
            float w6 = WhB[(size_t)j6*64 + u], w7 = WhB[(size_t)j7*64 + u];
            float p0 = fexp(lrelu(f1i + e0)), p1 = fexp(lrelu(f1i + e1));
            float p2 = fexp(lrelu(f1i + e2)), p3 = fexp(lrelu(f1i + e3));
            float p4 = fexp(lrelu(f1i + e4)), p5 = fexp(lrelu(f1i + e5));
            float p6 = fexp(lrelu(f1i + e6)), p7 = fexp(lrelu(f1i + e7));
            s += p0; s += p1; s += p2; s += p3;
            s += p4; s += p5; s += p6; s += p7;
            acc += p0*w0; acc += p1*w1; acc += p2*w2; acc += p3*w3;
            acc += p4*w4; acc += p5*w5; acc += p6*w6; acc += p7*w7;
        }
        for (; k < cnt; k++){
            int j = jl[k];
            float p = fexp(lrelu(f1i + f2B[j*8 + h]));
            s += p;
            acc += p * WhB[(size_t)j*64 + u];
        }
    } else {
        s = (float)N;
        for (int j = 0; j < N; j++) acc += WhB[(size_t)j*64 + u];
    }
    hs[g][u] = elu(acc / s);
    __syncthreads();

    // phase 2: Who[row][c] for c = u (first warp of each row pair)
    if (u < 32){
        int c = u;
        const float* hrow = hs[g];
        float who = 0.f;
#pragma unroll
        for (int f = 0; f < 64; f++) who += hrow[f] * Ws[f*32 + c];
        g_Who[(size_t)row*32 + c] = who;
        float v1 = who * a1s[c], v2 = who * a2s[c];
#pragma unroll
        for (int o = 16; o; o >>= 1){
            v1 += __shfl_xor_sync(0xffffffffu, v1, o);
            v2 += __shfl_xor_sync(0xffffffffu, v2, o);
        }
        if (c == 0){ g_g1[row] = v1; g_g2[row] = v2; }
    }
}

// ---------------- K4: layer-2 attention, lane=dim, chunk-8, writes outT ----------------
__global__ void k4_outattn(){
    int t = threadIdx.x, w = t >> 5, lane = t & 31;
    int row = blockIdx.x * 8 + w;       // = b*512 + i
    int b = row >> 9, i = row & 511;
    int cnt = g_cnt[row];
    const u16* __restrict__ jl = g_nbr + (size_t)row * N;

    float g1i = g_g1[row];
    const float* __restrict__ g2b  = g_g2 + b * N;
    const float* __restrict__ WhoB = g_Who + (size_t)b * N * DOUT;

    float s = 0.f, tot = 0.f;
    if (cnt > 0){
        int k = 0;
        for (; k + 8 <= cnt; k += 8){
            uint4 v = *(const uint4*)(jl + k);
            int j0 = v.x & 0xFFFF, j1 = v.x >> 16;
            int j2 = v.y & 0xFFFF, j3 = v.y >> 16;
            int j4 = v.z & 0xFFFF, j5 = v.z >> 16;
            int j6 = v.w & 0xFFFF, j7 = v.w >> 16;
            float e0 = g2b[j0], e1 = g2b[j1], e2 = g2b[j2], e3 = g2b[j3];
            float e4 = g2b[j4], e5 = g2b[j5], e6 = g2b[j6], e7 = g2b[j7];
            float w0 = WhoB[(size_t)j0*DOUT + lane], w1 = WhoB[(size_t)j1*DOUT + lane];
            float w2 = WhoB[(size_t)j2*DOUT + lane], w3 = WhoB[(size_t)j3*DOUT + lane];
            float w4 = WhoB[(size_t)j4*DOUT + lane], w5 = WhoB[(size_t)j5*DOUT + lane];
            float w6 = WhoB[(size_t)j6*DOUT + lane], w7 = WhoB[(size_t)j7*DOUT + lane];
            float p0 = fexp(lrelu(g1i + e0)), p1 = fexp(lrelu(g1i + e1));
            float p2 = fexp(lrelu(g1i + e2)), p3 = fexp(lrelu(g1i + e3));
            float p4 = fexp(lrelu(g1i + e4)), p5 = fexp(lrelu(g1i + e5));
            float p6 = fexp(lrelu(g1i + e6)), p7 = fexp(lrelu(g1i + e7));
            s += p0; s += p1; s += p2; s += p3;
            s += p4; s += p5; s += p6; s += p7;
            tot += p0*w0; tot += p1*w1; tot += p2*w2; tot += p3*w3;
            tot += p4*w4; tot += p5*w5; tot += p6*w6; tot += p7*w7;
        }
        for (; k < cnt; k++){
            int j = jl[k];
            float p = fexp(lrelu(g1i + g2b[j]));
            s += p;
            tot += p * WhoB[(size_t)j*DOUT + lane];
        }
    } else {
        s = (float)N;
        for (int j = 0; j < N; j++) tot += WhoB[(size_t)j*DOUT + lane];
    }
    g_outT[(size_t)(i*32 + lane)*B + b] = elu(tot / s);
}

// ---------------- K5: register-tiled GEMM  q = out[32,16384] @ Wq[16384,512] ----------------
__global__ void k5_qgemm(const float* __restrict__ Wq){
    __shared__ float outS[64*32];   // [k][b]  8 KB
    __shared__ float wqS[64*64];    // [k][c] 16 KB
    int t = threadIdx.x;
    int slice = t >> 6;             // 0..3
    int u = t & 63;
    int tx = u & 7;
    int ty = u >> 3;
    int b0 = ty*4, c0 = tx*8;
    int cb = blockIdx.x;
    int ky = blockIdx.y;
    int k0blk = ky * 512;

    ull acc2[16];
#pragma unroll
    for (int q = 0; q < 16; q++) acc2[q] = 0ull;

    for (int st = 0; st < 8; st++){
        int k0 = k0blk + st*64;
        __syncthreads();
        {
            const float4* src = (const float4*)(g_outT + (size_t)k0*32);
            float4* dst = (float4*)outS;
            dst[t]       = src[t];
            dst[t + 256] = src[t + 256];
        }
#pragma unroll
        for (int i = 0; i < 4; i++){
            int lin = t + i*256;
            int kk = lin >> 4;
            int cq = lin & 15;
            ((float4*)wqS)[kk*16 + cq] =
                *(const float4*)(Wq + (size_t)(k0 + kk)*512 + cb*64 + cq*4);
        }
        __syncthreads();

        const float* oS = outS + slice*16*32;
        const float* wS = wqS  + slice*16*64;
#pragma unroll
        for (int kk = 0; kk < 16; kk++){
            float4 o4 = *(const float4*)(oS + kk*32 + b0);
            ull ob0 = pack2(o4.x), ob1 = pack2(o4.y), ob2 = pack2(o4.z), ob3 = pack2(o4.w);
            const ull* w2 = (const ull*)(wS + kk*64 + c0);
#pragma unroll
            for (int cp = 0; cp < 4; cp++){
                ull wv = w2[cp];
                acc2[0*4+cp] = fma2(ob0, wv, acc2[0*4+cp]);
                acc2[1*4+cp] = fma2(ob1, wv, acc2[1*4+cp]);
                acc2[2*4+cp] = fma2(ob2, wv, acc2[2*4+cp]);
                acc2[3*4+cp] = fma2(ob3, wv, acc2[3*4+cp]);
            }
        }
    }
    float* qp = g_qpart + (size_t)(ky*4 + slice) * (B*N);
#pragma unroll
    for (int bb = 0; bb < 4; bb++)
#pragma unroll
        for (int cp = 0; cp < 4; cp++){
            float lo, hi; unpack2(acc2[bb*4+cp], lo, hi);
            int c = cb*64 + c0 + cp*2;
            qp[(b0+bb)*N + c]     = lo;
            qp[(b0+bb)*N + c + 1] = hi;
        }
}

// ---------------- K6: q = sum of 128 partials + b_q (float4) ----------------
__global__ void k6_reduce(const float* __restrict__ bq, float* __restrict__ q){
    int t4 = blockIdx.x * 128 + threadIdx.x;   // [0, 4096) float4 units
    int c4 = t4 & 127;                          // float4 col index within 512
    float4 s = ((const float4*)bq)[c4];
#pragma unroll
    for (int p = 0; p < 128; p++){
        float4 v = ((const float4*)(g_qpart + (size_t)p*(B*N)))[t4];
        s.x += v.x; s.y += v.y; s.z += v.z; s.w += v.w;
    }
    ((float4*)q)[t4] = s;
}

// ---------------- launch ----------------
extern "C" void kernel_launch(void* const* d_in, const int* in_sizes, int n_in,
                              void* d_out, int out_size){
    const float* xv    = (const float*)d_in[0];
    const float* adj   = (const float*)d_in[1];
    const float* Whead = (const float*)d_in[2];
    const float* a1    = (const float*)d_in[3];
    const float* a2    = (const float*)d_in[4];
    const float* Wout  = (const float*)d_in[5];
    const float* a1o   = (const float*)d_in[6];
    const float* a2o   = (const float*)d_in[7];
    const float* Wq    = (const float*)d_in[8];
    const float* bq    = (const float*)d_in[9];
    float* q = (float*)d_out;

    k0_compact<<<B*N/8, 256>>>(adj);
    k1_proj   <<<512, 256>>>(xv, Whead, a1, a2);
    k2_fused  <<<B*N/4, 256>>>(Wout, a1o, a2o);
    k4_outattn<<<B*N/8, 256>>>();
    k5_qgemm  <<<dim3(8, 32), 256>>>(Wq);
    k6_reduce <<<32, 128>>>(bq, q);
}